// round 10
// baseline (speedup 1.0000x reference)
#include <cuda_runtime.h>
#include <cuda_fp16.h>
#include <math.h>
#include <stdint.h>

// ---------------------------------------------------------------------------
// GAT layer, N=8192, Fin=Fout=256.
//   h = X@W; s1 = h@a[:256]; s2 = h@a[256:]
//   e_ij = LeakyReLU(s1_i+s2_j), adj-masked row softmax, out = ELU(P @ h)
// Tricks:
//   m_i = LR(s1_i + max s2) is a valid softmax shift (LR monotone) -> adj once.
//   exp(LR(t)-m) factorizes: t>=0 -> A_i*C_j ; t<0 -> B_i*D_j  (no exp in loop)
//   PV GEMM: fp16 m16n8k16 mma.sync (tcgen05 not available: harness PTX pass
//   targets compute_103 without the 'a' feature set).
// ---------------------------------------------------------------------------

#define N_NODES 8192
#define FDIM    256
#define ALPHA   0.2f

__device__ float  g_h [N_NODES * FDIM];   // fp32 h (for s1/s2)
__device__ __half g_hh[N_NODES * FDIM];   // half h (for PV mma)
__device__ float  g_s1[N_NODES];
__device__ float  g_s2[N_NODES];
__device__ float2 g_cd[N_NODES];          // (exp(s2), exp(0.2*s2))
__device__ float  g_s2max;

// ---------------------------------------------------------------------------
// K1: h = X @ W  (fp32 + half copies)
// ---------------------------------------------------------------------------
#define BM 64
#define BN 64
#define BK 16

__global__ void __launch_bounds__(256) gemm_xw(const float* __restrict__ X,
                                               const float* __restrict__ W) {
    __shared__ float As[BK][BM + 4];
    __shared__ float Bs[BK][BN + 4];
    int tid = threadIdx.x;
    int m0 = blockIdx.y * BM;
    int n0 = blockIdx.x * BN;
    int tx = tid & 15, ty = tid >> 4;

    float acc[4][4];
#pragma unroll
    for (int i = 0; i < 4; i++)
#pragma unroll
        for (int j = 0; j < 4; j++) acc[i][j] = 0.f;

    for (int kt = 0; kt < FDIM; kt += BK) {
        {
            int r = tid >> 2, k4 = (tid & 3) * 4;
            float4 v = *(const float4*)(X + (size_t)(m0 + r) * FDIM + kt + k4);
            As[k4 + 0][r] = v.x; As[k4 + 1][r] = v.y;
            As[k4 + 2][r] = v.z; As[k4 + 3][r] = v.w;
        }
        {
            int r = tid >> 4, c4 = (tid & 15) * 4;
            *(float4*)&Bs[r][c4] = *(const float4*)(W + (size_t)(kt + r) * FDIM + n0 + c4);
        }
        __syncthreads();
#pragma unroll
        for (int k = 0; k < BK; k++) {
            float4 a4 = *(const float4*)&As[k][ty * 4];
            float4 b4 = *(const float4*)&Bs[k][tx * 4];
            float a[4] = {a4.x, a4.y, a4.z, a4.w};
            float b[4] = {b4.x, b4.y, b4.z, b4.w};
#pragma unroll
            for (int i = 0; i < 4; i++)
#pragma unroll
                for (int j = 0; j < 4; j++) acc[i][j] = fmaf(a[i], b[j], acc[i][j]);
        }
        __syncthreads();
    }
#pragma unroll
    for (int i = 0; i < 4; i++)
#pragma unroll
        for (int j = 0; j < 4; j++) {
            size_t idx = (size_t)(m0 + ty * 4 + i) * FDIM + n0 + tx * 4 + j;
            float v = acc[i][j];
            g_h[idx]  = v;
            g_hh[idx] = __float2half(v);
        }
}

// ---------------------------------------------------------------------------
// K2: s1/s2 row dots + per-node (C, D) = (exp(s2), exp(0.2*s2))
// ---------------------------------------------------------------------------
__global__ void __launch_bounds__(256) compute_s(const float* __restrict__ a) {
    int warp = threadIdx.x >> 5;
    int lane = threadIdx.x & 31;
    int row = blockIdx.x * 8 + warp;
    const float* hr = g_h + (size_t)row * FDIM;
    float d1 = 0.f, d2 = 0.f;
#pragma unroll
    for (int q = 0; q < 2; q++) {
        int c = lane * 4 + q * 128;
        float4 h4 = *(const float4*)(hr + c);
        float4 a1 = *(const float4*)(a + c);
        float4 a2 = *(const float4*)(a + FDIM + c);
        d1 += h4.x * a1.x + h4.y * a1.y + h4.z * a1.z + h4.w * a1.w;
        d2 += h4.x * a2.x + h4.y * a2.y + h4.z * a2.z + h4.w * a2.w;
    }
#pragma unroll
    for (int off = 16; off > 0; off >>= 1) {
        d1 += __shfl_xor_sync(0xFFFFFFFFu, d1, off);
        d2 += __shfl_xor_sync(0xFFFFFFFFu, d2, off);
    }
    if (lane == 0) {
        g_s1[row] = d1;
        g_s2[row] = d2;
        g_cd[row] = make_float2(expf(d2), expf(ALPHA * d2));
    }
}

// ---------------------------------------------------------------------------
// K3: global max of s2
// ---------------------------------------------------------------------------
__global__ void __launch_bounds__(1024) s2max_kernel() {
    __shared__ float sm[1024];
    float m = -INFINITY;
    for (int i = threadIdx.x; i < N_NODES; i += 1024) m = fmaxf(m, g_s2[i]);
    sm[threadIdx.x] = m;
    __syncthreads();
    for (int s = 512; s > 0; s >>= 1) {
        if (threadIdx.x < s) sm[threadIdx.x] = fmaxf(sm[threadIdx.x], sm[threadIdx.x + s]);
        __syncthreads();
    }
    if (threadIdx.x == 0) g_s2max = sm[0];
}

// ---------------------------------------------------------------------------
// K4: fused masked-softmax @ h, fp16 m16n8k16 mma + ldmatrix, ELU.
//   MT=64 rows/CTA, grid=128, 512 thr = 16 warps (2 m x 8 n).
//   Double-buffered P/H smem tiles, ONE syncthreads per 64-j chunk:
//     body(kc): LDG(kc+1) -> mma(kc, buf) -> produce+STS(kc+1, buf^1) -> sync
//   P production uses factorized exp (no MUFU in the loop).
// ---------------------------------------------------------------------------
#define MT   64
#define KT   64
#define NCHUNK (N_NODES / KT)
#define PSTR 72       // halves; 144 B stride -> conflict-free ldmatrix
#define HSTR 264      // halves; 528 B stride -> conflict-free ldmatrix
#define PS_BYTES (MT * PSTR * 2)          // 9216
#define HS_BYTES (KT * HSTR * 2)          // 33792
#define ZS_OFF   (2 * PS_BYTES + 2 * HS_BYTES)         // 86016
#define SMEM_BYTES (ZS_OFF + MT * 4)                   // 86272

__device__ __forceinline__ void ldsm_x4(unsigned& r0, unsigned& r1,
                                        unsigned& r2, unsigned& r3, unsigned addr) {
    asm volatile("ldmatrix.sync.aligned.m8n8.x4.shared.b16 {%0,%1,%2,%3}, [%4];"
                 : "=r"(r0), "=r"(r1), "=r"(r2), "=r"(r3) : "r"(addr));
}

__device__ __forceinline__ void ldsm_x4_t(unsigned& r0, unsigned& r1,
                                          unsigned& r2, unsigned& r3, unsigned addr) {
    asm volatile("ldmatrix.sync.aligned.m8n8.x4.trans.shared.b16 {%0,%1,%2,%3}, [%4];"
                 : "=r"(r0), "=r"(r1), "=r"(r2), "=r"(r3) : "r"(addr));
}

__device__ __forceinline__ void mma_f16(float* c, unsigned a0, unsigned a1,
                                        unsigned a2, unsigned a3,
                                        unsigned b0, unsigned b1) {
    asm volatile(
        "mma.sync.aligned.m16n8k16.row.col.f32.f16.f16.f32 "
        "{%0,%1,%2,%3}, {%4,%5,%6,%7}, {%8,%9}, {%0,%1,%2,%3};"
        : "+f"(c[0]), "+f"(c[1]), "+f"(c[2]), "+f"(c[3])
        : "r"(a0), "r"(a1), "r"(a2), "r"(a3), "r"(b0), "r"(b1));
}

__global__ void __launch_bounds__(512, 1) gat_fused(const int* __restrict__ adj,
                                                    float* __restrict__ out) {
    extern __shared__ char smem[];
    // layout: Ps0 | Ps1 | Hs0 | Hs1 | Zs
    __half* Ps0 = (__half*)smem;
    __half* Hs0 = (__half*)(smem + 2 * PS_BYTES);
    float*  Zs  = (float*)(smem + ZS_OFF);

    int tid = threadIdx.x;
    int rowBase = blockIdx.x * MT;

    // P-production mapping: row pr (8 threads/row), 8 j per thread at pcg*8
    int pr = tid >> 3;
    int pcg = tid & 7;
    float s1r = g_s1[rowBase + pr];
    float tm = s1r + g_s2max;
    float mr = tm >= 0.f ? tm : ALPHA * tm;   // valid softmax shift
    float Ai = expf(s1r - mr);
    float Bi = expf(ALPHA * s1r - mr);
    float Ti = expf(-s1r);                     // C_j >= Ti  <=>  s1+s2 >= 0
    float zacc = 0.f;
    const int*   adjRow = adj + (size_t)(rowBase + pr) * N_NODES + pcg * 8;
    const float4* cdBase = (const float4*)(g_cd);   // 2 floats per node

    int warp = tid >> 5, lane = tid & 31;
    int wm = warp >> 3, wn = warp & 7;
    int lr = lane >> 2, lc = lane & 3;

    // ldmatrix base addresses (buffer 0)
    unsigned psBase = (unsigned)__cvta_generic_to_shared(Ps0);
    unsigned hsBase = (unsigned)__cvta_generic_to_shared(Hs0);
    int lg = lane & 15, lh = (lane >> 4) << 3;
    unsigned aAddr[2];
#pragma unroll
    for (int mt = 0; mt < 2; mt++)
        aAddr[mt] = psBase + ((wm * 32 + mt * 16 + lg) * PSTR + lh) * 2;
    unsigned bAddr[2];
#pragma unroll
    for (int ntp = 0; ntp < 2; ntp++)
        bAddr[ntp] = hsBase + (lg * HSTR + wn * 32 + ntp * 16 + lh) * 2;

    float c[2][4][4];
#pragma unroll
    for (int mt = 0; mt < 2; mt++)
#pragma unroll
        for (int nt = 0; nt < 4; nt++)
#pragma unroll
            for (int q = 0; q < 4; q++) c[mt][nt][q] = 0.f;

    // prefetch registers
    int4   aReg[2];    // adj: 8 ints
    float4 cdReg[4];   // (C,D) pairs for 8 j
    uint4  hReg[4];    // H: 32 halves

    // H store mapping: uint4 #(q*512+tid): row jr, col (tid&31)*8
    int hRowOff[4], hColOff = (tid & 31) * 8;
#pragma unroll
    for (int q = 0; q < 4; q++) hRowOff[q] = (q * 512 + tid) >> 5;

    // ---- prologue: LDG chunk 0, produce into buffer 0 ----
#pragma unroll
    for (int q = 0; q < 2; q++) aReg[q] = *(const int4*)(adjRow + q * 4);
#pragma unroll
    for (int q = 0; q < 4; q++) cdReg[q] = cdBase[(pcg * 8) / 2 + q];
#pragma unroll
    for (int q = 0; q < 4; q++)
        hReg[q] = *(const uint4*)(g_hh + (size_t)hRowOff[q] * FDIM + hColOff);
    // NOTE: hReg above indexes g_hh rows 0..63 (chunk 0), cols = feature.
    // g_hh row-major [node][feat]: node j = hRowOff, feat = hColOff.

    {
        // produce P(0), H(0) into buffer 0
        float pv[8];
#pragma unroll
        for (int q = 0; q < 2; q++) {
            int4 av = aReg[q];
            float4 cd0 = cdReg[q * 2], cd1 = cdReg[q * 2 + 1];
            float Cv[4] = {cd0.x, cd0.z, cd1.x, cd1.z};
            float Dv[4] = {cd0.y, cd0.w, cd1.y, cd1.w};
            int msk[4] = {av.x, av.y, av.z, av.w};
#pragma unroll
            for (int l = 0; l < 4; l++) {
                float val = (Cv[l] >= Ti) ? (Ai * Cv[l]) : (Bi * Dv[l]);
                val = (msk[l] > 0) ? val : 0.f;
                zacc += val;
                pv[q * 4 + l] = val;
            }
        }
        uint4 pk;
        __half2 t;
        t = __floats2half2_rn(pv[0], pv[1]); pk.x = *(unsigned*)&t;
        t = __floats2half2_rn(pv[2], pv[3]); pk.y = *(unsigned*)&t;
        t = __floats2half2_rn(pv[4], pv[5]); pk.z = *(unsigned*)&t;
        t = __floats2half2_rn(pv[6], pv[7]); pk.w = *(unsigned*)&t;
        *(uint4*)(Ps0 + pr * PSTR + pcg * 8) = pk;
#pragma unroll
        for (int q = 0; q < 4; q++)
            *(uint4*)(Hs0 + hRowOff[q] * HSTR + hColOff) = hReg[q];
    }
    __syncthreads();

    for (int kc = 0; kc < NCHUNK; kc++) {
        int bsel = kc & 1;
        int jn = (kc + 1 < NCHUNK) ? (kc + 1) * KT : 0;   // clamp avoids OOB

        // ---- 1. issue LDG for chunk kc+1 (latency hides under mma) ----
#pragma unroll
        for (int q = 0; q < 2; q++) aReg[q] = *(const int4*)(adjRow + jn + q * 4);
#pragma unroll
        for (int q = 0; q < 4; q++) cdReg[q] = cdBase[(jn + pcg * 8) / 2 + q];
#pragma unroll
        for (int q = 0; q < 4; q++)
            hReg[q] = *(const uint4*)(g_hh + (size_t)(jn + hRowOff[q]) * FDIM + hColOff);

        // ---- 2. mma chunk kc from buffer bsel ----
        unsigned pOff = bsel ? PS_BYTES : 0;
        unsigned hOff = bsel ? HS_BYTES : 0;
#pragma unroll
        for (int k = 0; k < 4; k++) {
            unsigned b[2][4];
#pragma unroll
            for (int ntp = 0; ntp < 2; ntp++)
                ldsm_x4_t(b[ntp][0], b[ntp][1], b[ntp][2], b[ntp][3],
                          bAddr[ntp] + hOff + k * 16 * HSTR * 2);
#pragma unroll
            for (int mt = 0; mt < 2; mt++) {
                unsigned a0, a1, a2, a3;
                ldsm_x4(a0, a1, a2, a3, aAddr[mt] + pOff + k * 32);
#pragma unroll
                for (int ntp = 0; ntp < 2; ntp++) {
                    mma_f16(c[mt][ntp * 2 + 0], a0, a1, a2, a3, b[ntp][0], b[ntp][1]);
                    mma_f16(c[mt][ntp * 2 + 1], a0, a1, a2, a3, b[ntp][2], b[ntp][3]);
                }
            }
        }

        // ---- 3. produce chunk kc+1 into buffer bsel^1 ----
        if (kc + 1 < NCHUNK) {
            __half* Pb = Ps0 + (bsel ? 0 : PS_BYTES / 2);
            __half* Hb = Hs0 + (bsel ? 0 : HS_BYTES / 2);
            float pv[8];
#pragma unroll
            for (int q = 0; q < 2; q++) {
                int4 av = aReg[q];
                float4 cd0 = cdReg[q * 2], cd1 = cdReg[q * 2 + 1];
                float Cv[4] = {cd0.x, cd0.z, cd1.x, cd1.z};
                float Dv[4] = {cd0.y, cd0.w, cd1.y, cd1.w};
                int msk[4] = {av.x, av.y, av.z, av.w};
#pragma unroll
                for (int l = 0; l < 4; l++) {
                    float val = (Cv[l] >= Ti) ? (Ai * Cv[l]) : (Bi * Dv[l]);
                    val = (msk[l] > 0) ? val : 0.f;
                    zacc += val;
                    pv[q * 4 + l] = val;
                }
            }
            uint4 pk;
            __half2 t;
            t = __floats2half2_rn(pv[0], pv[1]); pk.x = *(unsigned*)&t;
            t = __floats2half2_rn(pv[2], pv[3]); pk.y = *(unsigned*)&t;
            t = __floats2half2_rn(pv[4], pv[5]); pk.z = *(unsigned*)&t;
            t = __floats2half2_rn(pv[6], pv[7]); pk.w = *(unsigned*)&t;
            *(uint4*)(Pb + pr * PSTR + pcg * 8) = pk;
#pragma unroll
            for (int q = 0; q < 4; q++)
                *(uint4*)(Hb + hRowOff[q] * HSTR + hColOff) = hReg[q];
        }

        // ---- 4. one barrier per chunk ----
        __syncthreads();
    }

    // ---- Z reduce: 8 threads per row ----
    float z = zacc;
    z += __shfl_xor_sync(0xFFFFFFFFu, z, 1);
    z += __shfl_xor_sync(0xFFFFFFFFu, z, 2);
    z += __shfl_xor_sync(0xFFFFFFFFu, z, 4);
    if ((tid & 7) == 0) Zs[pr] = z;
    __syncthreads();

    // ---- epilogue: /Z, ELU, store ----
#pragma unroll
    for (int mt = 0; mt < 2; mt++) {
        int r0 = wm * 32 + mt * 16 + lr;
        float iz0 = 1.f / Zs[r0];
        float iz1 = 1.f / Zs[r0 + 8];
#pragma unroll
        for (int nt = 0; nt < 4; nt++) {
            int col = wn * 32 + nt * 8 + lc * 2;
            float v0 = c[mt][nt][0] * iz0;
            float v1 = c[mt][nt][1] * iz0;
            float v2 = c[mt][nt][2] * iz1;
            float v3 = c[mt][nt][3] * iz1;
            v0 = v0 > 0.f ? v0 : (__expf(v0) - 1.f);
            v1 = v1 > 0.f ? v1 : (__expf(v1) - 1.f);
            v2 = v2 > 0.f ? v2 : (__expf(v2) - 1.f);
            v3 = v3 > 0.f ? v3 : (__expf(v3) - 1.f);
            size_t o0 = (size_t)(rowBase + r0) * FDIM + col;
            size_t o1 = (size_t)(rowBase + r0 + 8) * FDIM + col;
            out[o0] = v0; out[o0 + 1] = v1;
            out[o1] = v2; out[o1 + 1] = v3;
        }
    }
}

// ---------------------------------------------------------------------------
extern "C" void kernel_launch(void* const* d_in, const int* in_sizes, int n_in,
                              void* d_out, int out_size) {
    const float* X   = (const float*)d_in[0];   // [8192,256]
    const int*   adj = (const int*)d_in[1];     // [8192,8192]
    const float* W   = (const float*)d_in[2];   // [256,256]
    const float* a   = (const float*)d_in[3];   // [512,1]
    float* out = (float*)d_out;                 // [8192,256]

    gemm_xw<<<dim3(FDIM / BN, N_NODES / BM), 256>>>(X, W);
    compute_s<<<N_NODES / 8, 256>>>(a);
    s2max_kernel<<<1, 1024>>>();

    cudaFuncSetAttribute(gat_fused, cudaFuncAttributeMaxDynamicSharedMemorySize,
                         SMEM_BYTES);
    gat_fused<<<N_NODES / MT, 512, SMEM_BYTES>>>(adj, out);
}

// round 11
// speedup vs baseline: 2.1252x; 2.1252x over previous
#include <cuda_runtime.h>
#include <cuda_fp16.h>
#include <math.h>
#include <stdint.h>

// ---------------------------------------------------------------------------
// GAT layer, N=8192, Fin=Fout=256.
//   h = X@W; s1 = h@a[:256]; s2 = h@a[256:]
//   e_ij = LeakyReLU(s1_i+s2_j), adj-masked row softmax, out = ELU(P @ h)
// Tricks:
//   m_i = LR(s1_i + max s2) is a valid softmax shift (LR monotone) -> adj once.
//   exp(LR(t)-m) factorizes: t>=0 -> A_i*C_j ; t<0 -> B_i*D_j  (no exp in loop)
//   PV GEMM: fp16 m16n8k16 mma.sync + ldmatrix (tcgen05 unavailable: the
//   harness PTX pass targets compute_103 without the 'a' feature set).
// Pipeline structure = R8 (produce/STS -> sync -> prefetch -> mma -> sync):
//   prefetch-to-consume distance spans the whole mma loop + barrier.
// ---------------------------------------------------------------------------

#define N_NODES 8192
#define FDIM    256
#define ALPHA   0.2f

__device__ float  g_h [N_NODES * FDIM];   // fp32 h (for s1/s2)
__device__ __half g_hh[N_NODES * FDIM];   // half h (for PV mma)
__device__ float  g_s1[N_NODES];
__device__ float  g_s2[N_NODES];
__device__ float  g_C[N_NODES];           // exp(s2)
__device__ float  g_D[N_NODES];           // exp(0.2*s2)
__device__ float  g_s2max;

// ---------------------------------------------------------------------------
// K1: h = X @ W  (fp32 + half copies)
// ---------------------------------------------------------------------------
#define BM 64
#define BN 64
#define BK 16

__global__ void __launch_bounds__(256) gemm_xw(const float* __restrict__ X,
                                               const float* __restrict__ W) {
    __shared__ float As[BK][BM + 4];
    __shared__ float Bs[BK][BN + 4];
    int tid = threadIdx.x;
    int m0 = blockIdx.y * BM;
    int n0 = blockIdx.x * BN;
    int tx = tid & 15, ty = tid >> 4;

    float acc[4][4];
#pragma unroll
    for (int i = 0; i < 4; i++)
#pragma unroll
        for (int j = 0; j < 4; j++) acc[i][j] = 0.f;

    for (int kt = 0; kt < FDIM; kt += BK) {
        {
            int r = tid >> 2, k4 = (tid & 3) * 4;
            float4 v = *(const float4*)(X + (size_t)(m0 + r) * FDIM + kt + k4);
            As[k4 + 0][r] = v.x; As[k4 + 1][r] = v.y;
            As[k4 + 2][r] = v.z; As[k4 + 3][r] = v.w;
        }
        {
            int r = tid >> 4, c4 = (tid & 15) * 4;
            *(float4*)&Bs[r][c4] = *(const float4*)(W + (size_t)(kt + r) * FDIM + n0 + c4);
        }
        __syncthreads();
#pragma unroll
        for (int k = 0; k < BK; k++) {
            float4 a4 = *(const float4*)&As[k][ty * 4];
            float4 b4 = *(const float4*)&Bs[k][tx * 4];
            float a[4] = {a4.x, a4.y, a4.z, a4.w};
            float b[4] = {b4.x, b4.y, b4.z, b4.w};
#pragma unroll
            for (int i = 0; i < 4; i++)
#pragma unroll
                for (int j = 0; j < 4; j++) acc[i][j] = fmaf(a[i], b[j], acc[i][j]);
        }
        __syncthreads();
    }
#pragma unroll
    for (int i = 0; i < 4; i++)
#pragma unroll
        for (int j = 0; j < 4; j++) {
            size_t idx = (size_t)(m0 + ty * 4 + i) * FDIM + n0 + tx * 4 + j;
            float v = acc[i][j];
            g_h[idx]  = v;
            g_hh[idx] = __float2half(v);
        }
}

// ---------------------------------------------------------------------------
// K2: s1/s2 row dots + per-node C = exp(s2), D = exp(0.2*s2)
// ---------------------------------------------------------------------------
__global__ void __launch_bounds__(256) compute_s(const float* __restrict__ a) {
    int warp = threadIdx.x >> 5;
    int lane = threadIdx.x & 31;
    int row = blockIdx.x * 8 + warp;
    const float* hr = g_h + (size_t)row * FDIM;
    float d1 = 0.f, d2 = 0.f;
#pragma unroll
    for (int q = 0; q < 2; q++) {
        int c = lane * 4 + q * 128;
        float4 h4 = *(const float4*)(hr + c);
        float4 a1 = *(const float4*)(a + c);
        float4 a2 = *(const float4*)(a + FDIM + c);
        d1 += h4.x * a1.x + h4.y * a1.y + h4.z * a1.z + h4.w * a1.w;
        d2 += h4.x * a2.x + h4.y * a2.y + h4.z * a2.z + h4.w * a2.w;
    }
#pragma unroll
    for (int off = 16; off > 0; off >>= 1) {
        d1 += __shfl_xor_sync(0xFFFFFFFFu, d1, off);
        d2 += __shfl_xor_sync(0xFFFFFFFFu, d2, off);
    }
    if (lane == 0) {
        g_s1[row] = d1;
        g_s2[row] = d2;
        g_C[row] = expf(d2);
        g_D[row] = expf(ALPHA * d2);
    }
}

// ---------------------------------------------------------------------------
// K3: global max of s2
// ---------------------------------------------------------------------------
__global__ void __launch_bounds__(1024) s2max_kernel() {
    __shared__ float sm[1024];
    float m = -INFINITY;
    for (int i = threadIdx.x; i < N_NODES; i += 1024) m = fmaxf(m, g_s2[i]);
    sm[threadIdx.x] = m;
    __syncthreads();
    for (int s = 512; s > 0; s >>= 1) {
        if (threadIdx.x < s) sm[threadIdx.x] = fmaxf(sm[threadIdx.x], sm[threadIdx.x + s]);
        __syncthreads();
    }
    if (threadIdx.x == 0) g_s2max = sm[0];
}

// ---------------------------------------------------------------------------
// K4: fused masked-softmax @ h, fp16 m16n8k16 mma + ldmatrix, ELU.
//   MT=64 rows/CTA, grid=128, 512 thr = 16 warps (2 m x 8 n).
//   Per chunk (R8 structure): produce P/H from prefetched regs -> sync ->
//   issue prefetch of next chunk -> mma (ldmatrix) -> sync.
//   P production: factorized exp (no MUFU in the loop).
// ---------------------------------------------------------------------------
#define MT   64
#define KT   64
#define NCHUNK (N_NODES / KT)
#define PSTR 72       // halves; conflict-free ldmatrix
#define HSTR 264      // halves; conflict-free ldmatrix
#define PS_BYTES (MT * PSTR * 2)          // 9216
#define HS_BYTES (KT * HSTR * 2)          // 33792
#define CS_OFF   (PS_BYTES + HS_BYTES)                 // 43008
#define DS_OFF   (CS_OFF + N_NODES * 4)                // 75776
#define ZS_OFF   (DS_OFF + N_NODES * 4)                // 108544
#define SMEM_BYTES (ZS_OFF + MT * 4)                   // 108800

__device__ __forceinline__ void ldsm_x4(unsigned& r0, unsigned& r1,
                                        unsigned& r2, unsigned& r3, unsigned addr) {
    asm volatile("ldmatrix.sync.aligned.m8n8.x4.shared.b16 {%0,%1,%2,%3}, [%4];"
                 : "=r"(r0), "=r"(r1), "=r"(r2), "=r"(r3) : "r"(addr));
}

__device__ __forceinline__ void ldsm_x4_t(unsigned& r0, unsigned& r1,
                                          unsigned& r2, unsigned& r3, unsigned addr) {
    asm volatile("ldmatrix.sync.aligned.m8n8.x4.trans.shared.b16 {%0,%1,%2,%3}, [%4];"
                 : "=r"(r0), "=r"(r1), "=r"(r2), "=r"(r3) : "r"(addr));
}

__device__ __forceinline__ void mma_f16(float* c, unsigned a0, unsigned a1,
                                        unsigned a2, unsigned a3,
                                        unsigned b0, unsigned b1) {
    asm volatile(
        "mma.sync.aligned.m16n8k16.row.col.f32.f16.f16.f32 "
        "{%0,%1,%2,%3}, {%4,%5,%6,%7}, {%8,%9}, {%0,%1,%2,%3};"
        : "+f"(c[0]), "+f"(c[1]), "+f"(c[2]), "+f"(c[3])
        : "r"(a0), "r"(a1), "r"(a2), "r"(a3), "r"(b0), "r"(b1));
}

__global__ void __launch_bounds__(512, 1) gat_fused(const int* __restrict__ adj,
                                                    float* __restrict__ out) {
    extern __shared__ char smem[];
    __half* Ps  = (__half*)smem;                    // [64][72] halves
    __half* Hs  = (__half*)(smem + PS_BYTES);       // [64][264] halves
    float*  Cs  = (float*)(smem + CS_OFF);          // [8192] exp(s2)
    float*  Ds  = (float*)(smem + DS_OFF);          // [8192] exp(.2 s2)
    float*  Zs  = (float*)(smem + ZS_OFF);          // [64]

    int tid = threadIdx.x;
    int rowBase = blockIdx.x * MT;

    // preload C/D tables (reused 64x per CTA)
    {
        const float4* cs = (const float4*)g_C;
        const float4* ds = (const float4*)g_D;
        float4* cd = (float4*)Cs;
        float4* dd = (float4*)Ds;
#pragma unroll
        for (int q = 0; q < 4; q++) cd[q * 512 + tid] = cs[q * 512 + tid];
#pragma unroll
        for (int q = 0; q < 4; q++) dd[q * 512 + tid] = ds[q * 512 + tid];
    }

    // P-production mapping: row pr (8 threads/row), cols pcg*8..+8
    int pr = tid >> 3;
    int pcg = tid & 7;
    float s1r = g_s1[rowBase + pr];
    float tm = s1r + g_s2max;
    float mr = tm >= 0.f ? tm : ALPHA * tm;   // valid softmax shift
    float Ai = expf(s1r - mr);
    float Bi = expf(ALPHA * s1r - mr);
    float Ti = expf(-s1r);                     // C_j >= Ti  <=>  s1+s2 >= 0
    float zacc = 0.f;
    const int4* adjRow = (const int4*)(adj + (size_t)(rowBase + pr) * N_NODES);

    int warp = tid >> 5, lane = tid & 31;
    int wm = warp >> 3, wn = warp & 7;
    int lr = lane >> 2, lc = lane & 3;

    // ldmatrix base addresses
    unsigned psBase = (unsigned)__cvta_generic_to_shared(Ps);
    unsigned hsBase = (unsigned)__cvta_generic_to_shared(Hs);
    int lg = lane & 15, lh = (lane >> 4) << 3;
    unsigned aAddr[2];
#pragma unroll
    for (int mt = 0; mt < 2; mt++)
        aAddr[mt] = psBase + ((wm * 32 + mt * 16 + lg) * PSTR + lh) * 2;
    unsigned bAddr[2];
#pragma unroll
    for (int ntp = 0; ntp < 2; ntp++)
        bAddr[ntp] = hsBase + (lg * HSTR + wn * 32 + ntp * 16 + lh) * 2;

    float c[2][4][4];
#pragma unroll
    for (int mt = 0; mt < 2; mt++)
#pragma unroll
        for (int nt = 0; nt < 4; nt++)
#pragma unroll
            for (int q = 0; q < 4; q++) c[mt][nt][q] = 0.f;

    // ---- prefetch chunk 0 ----
    int4 aReg[2];
    uint4 hReg[4];
#pragma unroll
    for (int q = 0; q < 2; q++) aReg[q] = adjRow[pcg * 2 + q];
    {
        const uint4* hp = (const uint4*)g_hh;
#pragma unroll
        for (int q = 0; q < 4; q++) hReg[q] = hp[q * 512 + tid];
    }

    __syncthreads();   // Cs/Ds ready

    for (int kc = 0; kc < NCHUNK; kc++) {
        int j0 = kc * KT;

        // ---- P tile (fp16) from prefetched adj regs, factorized exp ----
        {
            int jb = j0 + pcg * 8;
            float4 Cv0 = *(const float4*)(Cs + jb);
            float4 Cv1 = *(const float4*)(Cs + jb + 4);
            float4 Dv0 = *(const float4*)(Ds + jb);
            float4 Dv1 = *(const float4*)(Ds + jb + 4);
            float Cv[8] = {Cv0.x, Cv0.y, Cv0.z, Cv0.w, Cv1.x, Cv1.y, Cv1.z, Cv1.w};
            float Dv[8] = {Dv0.x, Dv0.y, Dv0.z, Dv0.w, Dv1.x, Dv1.y, Dv1.z, Dv1.w};
            int msk[8] = {aReg[0].x, aReg[0].y, aReg[0].z, aReg[0].w,
                          aReg[1].x, aReg[1].y, aReg[1].z, aReg[1].w};
            float p[8];
#pragma unroll
            for (int l = 0; l < 8; l++) {
                float val = (Cv[l] >= Ti) ? (Ai * Cv[l]) : (Bi * Dv[l]);
                val = (msk[l] > 0) ? val : 0.f;
                zacc += val;
                p[l] = val;
            }
            uint4 pk;
            __half2 t;
            t = __floats2half2_rn(p[0], p[1]); pk.x = *(unsigned*)&t;
            t = __floats2half2_rn(p[2], p[3]); pk.y = *(unsigned*)&t;
            t = __floats2half2_rn(p[4], p[5]); pk.z = *(unsigned*)&t;
            t = __floats2half2_rn(p[6], p[7]); pk.w = *(unsigned*)&t;
            *(uint4*)(Ps + pr * PSTR + pcg * 8) = pk;
        }

        // ---- H tile (half) from prefetched regs ----
#pragma unroll
        for (int q = 0; q < 4; q++) {
            int jr = (q * 512 + tid) >> 5;
            int cch = (tid & 31) * 8;
            *(uint4*)(Hs + jr * HSTR + cch) = hReg[q];
        }
        __syncthreads();

        // ---- prefetch chunk kc+1 (consumed NEXT iteration; hides under mma) ----
        int jn = (kc + 1 < NCHUNK) ? j0 + KT : 0;
#pragma unroll
        for (int q = 0; q < 2; q++) aReg[q] = adjRow[jn / 4 + pcg * 2 + q];
        {
            const uint4* hp = (const uint4*)(g_hh + (size_t)jn * FDIM);
#pragma unroll
            for (int q = 0; q < 4; q++) hReg[q] = hp[q * 512 + tid];
        }

        // ---- mma: 4 k16-steps ----
#pragma unroll
        for (int k = 0; k < 4; k++) {
            unsigned b[2][4];
#pragma unroll
            for (int ntp = 0; ntp < 2; ntp++)
                ldsm_x4_t(b[ntp][0], b[ntp][1], b[ntp][2], b[ntp][3],
                          bAddr[ntp] + k * 16 * HSTR * 2);
#pragma unroll
            for (int mt = 0; mt < 2; mt++) {
                unsigned a0, a1, a2, a3;
                ldsm_x4(a0, a1, a2, a3, aAddr[mt] + k * 32);
#pragma unroll
                for (int ntp = 0; ntp < 2; ntp++) {
                    mma_f16(c[mt][ntp * 2 + 0], a0, a1, a2, a3, b[ntp][0], b[ntp][1]);
                    mma_f16(c[mt][ntp * 2 + 1], a0, a1, a2, a3, b[ntp][2], b[ntp][3]);
                }
            }
        }
        __syncthreads();
    }

    // ---- Z reduce: 8 threads per row ----
    float z = zacc;
    z += __shfl_xor_sync(0xFFFFFFFFu, z, 1);
    z += __shfl_xor_sync(0xFFFFFFFFu, z, 2);
    z += __shfl_xor_sync(0xFFFFFFFFu, z, 4);
    if ((tid & 7) == 0) Zs[pr] = z;
    __syncthreads();

    // ---- epilogue: /Z, ELU, store ----
#pragma unroll
    for (int mt = 0; mt < 2; mt++) {
        int r0 = wm * 32 + mt * 16 + lr;
        float iz0 = 1.f / Zs[r0];
        float iz1 = 1.f / Zs[r0 + 8];
#pragma unroll
        for (int nt = 0; nt < 4; nt++) {
            int col = wn * 32 + nt * 8 + lc * 2;
            float v0 = c[mt][nt][0] * iz0;
            float v1 = c[mt][nt][1] * iz0;
            float v2 = c[mt][nt][2] * iz1;
            float v3 = c[mt][nt][3] * iz1;
            v0 = v0 > 0.f ? v0 : (__expf(v0) - 1.f);
            v1 = v1 > 0.f ? v1 : (__expf(v1) - 1.f);
            v2 = v2 > 0.f ? v2 : (__expf(v2) - 1.f);
            v3 = v3 > 0.f ? v3 : (__expf(v3) - 1.f);
            size_t o0 = (size_t)(rowBase + r0) * FDIM + col;
            size_t o1 = (size_t)(rowBase + r0 + 8) * FDIM + col;
            out[o0] = v0; out[o0 + 1] = v1;
            out[o1] = v2; out[o1 + 1] = v3;
        }
    }
}

// ---------------------------------------------------------------------------
extern "C" void kernel_launch(void* const* d_in, const int* in_sizes, int n_in,
                              void* d_out, int out_size) {
    const float* X   = (const float*)d_in[0];   // [8192,256]
    const int*   adj = (const int*)d_in[1];     // [8192,8192]
    const float* W   = (const float*)d_in[2];   // [256,256]
    const float* a   = (const float*)d_in[3];   // [512,1]
    float* out = (float*)d_out;                 // [8192,256]

    gemm_xw<<<dim3(FDIM / BN, N_NODES / BM), 256>>>(X, W);
    compute_s<<<N_NODES / 8, 256>>>(a);
    s2max_kernel<<<1, 1024>>>();

    cudaFuncSetAttribute(gat_fused, cudaFuncAttributeMaxDynamicSharedMemorySize,
                         SMEM_BYTES);
    gat_fused<<<N_NODES / MT, 512, SMEM_BYTES>>>(adj, out);
}